// round 10
// baseline (speedup 1.0000x reference)
#include <cuda_runtime.h>
#include <cuda_fp16.h>
#include <cstdint>

#define T_CAP 64
#define BATCH 256
#define DEC   1024
#define HID   1024
#define ATTN  128
#define NBLK  128
#define NTHR  512

// ---------------- persistent scratch ----------------
__device__ float  g_Uv[BATCH * T_CAP * ATTN];   // 8 MB, [b][t][a]
__device__ float  g_h[2][BATCH * HID];          // fp32 hidden (attention)
__device__ __half g_h_h[2][BATCH * HID];        // fp16 hidden (gates GEMM)
__device__ float  g_c[BATCH * HID];             // cell state (block-private tiles)
__device__ __half g_ctx_h[BATCH * DEC];         // fp16 context (gates GEMM)
__device__ __half g_Wih_h[4 * HID * DEC];       // fp16 W_ih (8 MB)
__device__ __half g_Whh_h[4 * HID * HID];       // fp16 W_hh (8 MB)
__device__ int    g_cnt;
__device__ volatile int g_flag;

// ---------------- helpers ----------------
__device__ __forceinline__ uint32_t f2tf(float f) {
    uint32_t u;
    asm("cvt.rna.tf32.f32 %0, %1;" : "=r"(u) : "f"(f));
    return u;
}

__device__ __forceinline__ void mma8(float* c, const uint32_t* a, const uint32_t* b) {
    asm volatile(
        "mma.sync.aligned.m16n8k8.row.col.f32.tf32.tf32.f32 "
        "{%0,%1,%2,%3}, {%4,%5,%6,%7}, {%8,%9}, {%0,%1,%2,%3};\n"
        : "+f"(c[0]), "+f"(c[1]), "+f"(c[2]), "+f"(c[3])
        : "r"(a[0]), "r"(a[1]), "r"(a[2]), "r"(a[3]),
          "r"(b[0]), "r"(b[1]));
}

__device__ __forceinline__ void mma16(float* c, const uint32_t* a, const uint32_t* b) {
    asm volatile(
        "mma.sync.aligned.m16n8k16.row.col.f32.f16.f16.f32 "
        "{%0,%1,%2,%3}, {%4,%5,%6,%7}, {%8,%9}, {%0,%1,%2,%3};\n"
        : "+f"(c[0]), "+f"(c[1]), "+f"(c[2]), "+f"(c[3])
        : "r"(a[0]), "r"(a[1]), "r"(a[2]), "r"(a[3]),
          "r"(b[0]), "r"(b[1]));
}

__device__ __forceinline__ void ldsm4(uint32_t* r, uint32_t addr) {
    asm volatile("ldmatrix.sync.aligned.m8n8.x4.shared.b16 {%0,%1,%2,%3}, [%4];"
                 : "=r"(r[0]), "=r"(r[1]), "=r"(r[2]), "=r"(r[3]) : "r"(addr));
}

__device__ __forceinline__ uint32_t smem_u32(const void* p) {
    return (uint32_t)__cvta_generic_to_shared(p);
}
__device__ __forceinline__ void cp16(void* s, const void* g) {
    asm volatile("cp.async.ca.shared.global [%0], [%1], 16;\n" :: "r"(smem_u32(s)), "l"(g));
}
__device__ __forceinline__ void cp16cg(void* s, const void* g) {
    asm volatile("cp.async.cg.shared.global [%0], [%1], 16;\n" :: "r"(smem_u32(s)), "l"(g));
}
#define CP_COMMIT() asm volatile("cp.async.commit_group;\n" ::)
#define CP_WAIT(n)  asm volatile("cp.async.wait_group " #n ";\n" ::)

__device__ __forceinline__ float sigf(float x) { return 1.0f / (1.0f + __expf(-x)); }
__device__ __forceinline__ float tanh_fast(float x) {
    return __fdividef(2.0f, 1.0f + __expf(-2.0f * x)) - 1.0f;
}

#define SWZ(x) ((x) ^ (((x) >> 3) & 0x70))

// grid barrier (all NBLK blocks co-resident)
__device__ __forceinline__ void gsync(int* sense) {
    __syncthreads();
    int s = *sense ^ 1;
    *sense = s;
    if (threadIdx.x == 0) {
        __threadfence();
        if (atomicAdd(&g_cnt, 1) == NBLK - 1) {
            g_cnt = 0;
            __threadfence();
            g_flag = s;
        } else {
            while (g_flag != s) __nanosleep(32);
        }
        __threadfence();
    }
    __syncthreads();
}

// ---------------- Uv tile: 128(m) x 64(n) x 1024(k), one-time ----------------
__device__ __forceinline__ void uv_tile(
    float* smem, const float* __restrict__ dh, const float* __restrict__ U_attn,
    const float* __restrict__ b_attn, int m0, int n0)
{
    float (*As)[128][20] = (float(*)[128][20])smem;
    float (*Bs)[64][20]  = (float(*)[64][20])(smem + 5120);

    const int tid = threadIdx.x;
    const int warp = tid >> 5, lane = tid & 31;
    const int am = (tid & 255) >> 1, ak = (tid & 1) * 8;
    const int bj = (tid & 255) >> 2, bk = (tid & 3) * 4;
    const int r = m0 + am;
    const long abase = ((long)((r & 63) * 256 + (r >> 6))) * 1024;
    const long bbase = (long)(n0 + bj) * 1024;
    const bool ldr = tid < 256;

    const int wm = (warp >> 2) * 64, wn = (warp & 3) * 16;
    const int lr = lane >> 2, lc = lane & 3;

    float acc[4][2][4];
#pragma unroll
    for (int i = 0; i < 4; i++)
#pragma unroll
        for (int j = 0; j < 2; j++)
#pragma unroll
            for (int k = 0; k < 4; k++) acc[i][j][k] = 0.0f;

    const int NS = 64;
    if (ldr) {
        cp16(&As[0][am][ak],     dh + abase + ak);
        cp16(&As[0][am][ak + 4], dh + abase + ak + 4);
        cp16(&Bs[0][bj][bk],     U_attn + bbase + bk);
    }
    CP_COMMIT();

    for (int s = 0; s < NS; s++) {
        if (s + 1 < NS) {
            int buf = (s + 1) & 1, k0 = (s + 1) * 16;
            if (ldr) {
                cp16(&As[buf][am][ak],     dh + abase + k0 + ak);
                cp16(&As[buf][am][ak + 4], dh + abase + k0 + ak + 4);
                cp16(&Bs[buf][bj][bk],     U_attn + bbase + k0 + bk);
            }
            CP_COMMIT();
            CP_WAIT(1);
        } else {
            CP_WAIT(0);
        }
        __syncthreads();
        if (warp < 8) {
            const int buf = s & 1;
#pragma unroll
            for (int kk = 0; kk < 16; kk += 8) {
                uint32_t af[4][4], bf[2][2];
#pragma unroll
                for (int fm = 0; fm < 4; fm++) {
                    int rr = wm + fm * 16 + lr;
                    af[fm][0] = f2tf(As[buf][rr][kk + lc]);
                    af[fm][1] = f2tf(As[buf][rr + 8][kk + lc]);
                    af[fm][2] = f2tf(As[buf][rr][kk + lc + 4]);
                    af[fm][3] = f2tf(As[buf][rr + 8][kk + lc + 4]);
                }
#pragma unroll
                for (int fn = 0; fn < 2; fn++) {
                    int jc = wn + fn * 8 + lr;
                    bf[fn][0] = f2tf(Bs[buf][jc][kk + lc]);
                    bf[fn][1] = f2tf(Bs[buf][jc][kk + lc + 4]);
                }
#pragma unroll
                for (int fm = 0; fm < 4; fm++)
#pragma unroll
                    for (int fn = 0; fn < 2; fn++) mma8(acc[fm][fn], af[fm], bf[fn]);
            }
        }
        __syncthreads();
    }

    if (warp < 8) {
#pragma unroll
        for (int fm = 0; fm < 4; fm++) {
#pragma unroll
            for (int fn = 0; fn < 2; fn++) {
                int rr = m0 + wm + fm * 16 + lr;
                int a  = n0 + wn + fn * 8 + 2 * lc;
                float ba0 = b_attn[a], ba1 = b_attn[a + 1];
                float2 v0 = make_float2(acc[fm][fn][0] + ba0, acc[fm][fn][1] + ba1);
                float2 v1 = make_float2(acc[fm][fn][2] + ba0, acc[fm][fn][3] + ba1);
                *(float2*)&g_Uv[rr * ATTN + a]       = v0;
                *(float2*)&g_Uv[(rr + 8) * ATTN + a] = v1;
            }
        }
    }
}

// smem (bytes): A stages 8 x 16KB = 128KB ; B stages 8 x 8KB = 64KB
#define SM_A(sl)  ((sl) * 16384)
#define SM_B(sl)  (131072 + (sl) * 8192)
#define GK_SMEM_BYTES 196608

// ---------------- the persistent kernel ----------------
__global__ __launch_bounds__(NTHR, 1) void recon_kernel(
    const float* __restrict__ dh, const int* __restrict__ caps,
    const float* __restrict__ W_attn, const float* __restrict__ U_attn,
    const float* __restrict__ b_attn, const float* __restrict__ w_attn,
    const float* __restrict__ W_ih, const float* __restrict__ W_hh,
    const float* __restrict__ b_ih, const float* __restrict__ b_hh,
    float* __restrict__ out, int T_feat)
{
    extern __shared__ __align__(1024) float smem[];
    __shared__ float bias_s[64];

    const int tid = threadIdx.x, blk = blockIdx.x;
    const int warp = tid >> 5, lane = tid & 31;
    int sense = 0;

    const int gm0 = (blk & 1) * 128;
    const int gn0 = (blk >> 1) * 16;

    char* smem_c = (char*)smem;
    const uint32_t smem_base = smem_u32(smem);

    if (tid < 64) {
        int row = (tid & 3) * 1024 + gn0 + (tid >> 2);
        bias_s[tid] = b_ih[row] + b_hh[row];
    }

    // ---- phase 0 ----
    for (int i = blk * NTHR + tid; i < BATCH * HID; i += NBLK * NTHR) {
        g_h[0][i]   = 0.0f;
        g_h_h[0][i] = __float2half_rn(0.0f);
        g_c[i]      = 0.0f;
    }
    for (int i = blk * NTHR + tid; i < 4 * HID * DEC; i += NBLK * NTHR)
        g_Wih_h[i] = __float2half_rn(W_ih[i]);
    for (int i = blk * NTHR + tid; i < 4 * HID * HID; i += NBLK * NTHR)
        g_Whh_h[i] = __float2half_rn(W_hh[i]);
    for (int tix = blk; tix < 256; tix += NBLK)
        uv_tile(smem, dh, U_attn, b_attn, (tix & 127) * 128, (tix >> 7) * 64);
    gsync(&sense);

    // ---- gates loaders: A 128 rows x 64k fp16 (16KB), B 64 j x 64k fp16 (8KB) ----
    const int a_row = tid >> 2;
    const int a_c   = (tid & 3) * 16;
    const long a_goff = (long)(gm0 + a_row) * 1024 + a_c;
    const int a_so  = a_row * 128 + a_c * 2;
    const int b_row = tid >> 3;
    const int b_c   = (tid & 7) * 8;
    const long b_goff = (long)((b_row & 3) * 1024 + gn0 + (b_row >> 2)) * 1024 + b_c;
    const int b_so  = b_row * 128 + b_c * 2;

    // ---- 4-way k-split: 4 groups x 4 warps; warp tile 64m x 32j ----
    const int grp = warp >> 2;          // group handles stages 4t+grp
    const int wg  = warp & 3;
    const int wm  = (wg & 1) * 64;
    const int wn  = (wg >> 1) * 32;
    const int ls_row = ((lane >> 3) & 1) * 8 + (lane & 7);
    const int ls_colb = (lane >> 4) * 16;
    const uint32_t a_swz = SWZ((uint32_t)((wm + ls_row) * 128 + ls_colb));
    const uint32_t b_swz = SWZ((uint32_t)((wn + ls_row) * 128 + ls_colb));
    const int lr = lane >> 2, lc = lane & 3;

    for (int s = 0; s < T_feat; s++) {
        const float*  hprev   = g_h[s & 1];
        const __half* hprev_h = g_h_h[s & 1];
        float*  hnext   = g_h[(s + 1) & 1];
        __half* hnext_h = g_h_h[(s + 1) & 1];

        // ================= attention: 2 batch rows per block (fp32 throughout) =================
        {
            const int b0 = blk * 2;
            float* hs  = smem;           // [2][1024]
            float* whs = smem + 2048;    // [2][128]
            float* wa  = smem + 2304;    // [128]
            float* es  = smem + 2432;    // [2][64]
            float* ps  = smem + 2560;    // [2][64]

            for (int i = tid; i < 2 * HID; i += NTHR)
                hs[i] = __ldcg(&hprev[b0 * HID + i]);
            if (tid < ATTN) wa[tid] = w_attn[tid];
            __syncthreads();

            const float4* h0v = (const float4*)hs;
            const float4* h1v = (const float4*)(hs + 1024);
#pragma unroll
            for (int rr = 0; rr < 8; rr++) {
                int a = warp * 8 + rr;
                const float4* wrow = (const float4*)(W_attn + a * 1024);
                float d0 = 0.f, d1 = 0.f;
#pragma unroll
                for (int j = 0; j < 8; j++) {
                    float4 w4 = wrow[lane + 32 * j];
                    float4 x4 = h0v[lane + 32 * j];
                    float4 y4 = h1v[lane + 32 * j];
                    d0 += w4.x * x4.x + w4.y * x4.y + w4.z * x4.z + w4.w * x4.w;
                    d1 += w4.x * y4.x + w4.y * y4.y + w4.z * y4.z + w4.w * y4.w;
                }
#pragma unroll
                for (int off = 16; off; off >>= 1) {
                    d0 += __shfl_xor_sync(0xffffffffu, d0, off);
                    d1 += __shfl_xor_sync(0xffffffffu, d1, off);
                }
                if (lane == 0) { whs[a] = d0; whs[128 + a] = d1; }
            }
            __syncthreads();

            for (int t = warp; t < T_CAP; t += 16) {
#pragma unroll
                for (int bi = 0; bi < 2; bi++) {
                    const float* uv = g_Uv + ((long)(b0 + bi) * T_CAP + t) * ATTN;
                    float sE = 0.f;
#pragma unroll
                    for (int q = 0; q < 4; q++) {
                        int a = lane + q * 32;
                        sE += wa[a] * tanh_fast(whs[bi * 128 + a] + uv[a]);
                    }
#pragma unroll
                    for (int off = 16; off; off >>= 1)
                        sE += __shfl_xor_sync(0xffffffffu, sE, off);
                    if (lane == 0) {
                        int cp = caps[t * BATCH + b0 + bi];
                        es[bi * 64 + t] = (cp != 0 && cp != 2) ? sE : -1e30f;
                    }
                }
            }
            __syncthreads();

            if (warp < 2) {
                int bi = warp;
                float e0 = es[bi * 64 + lane], e1 = es[bi * 64 + lane + 32];
                float mx = fmaxf(e0, e1);
#pragma unroll
                for (int off = 16; off; off >>= 1)
                    mx = fmaxf(mx, __shfl_xor_sync(0xffffffffu, mx, off));
                float x0 = __expf(e0 - mx), x1 = __expf(e1 - mx);
                float sm = x0 + x1;
#pragma unroll
                for (int off = 16; off; off >>= 1)
                    sm += __shfl_xor_sync(0xffffffffu, sm, off);
                float inv = 1.0f / sm;
                ps[bi * 64 + lane]      = x0 * inv;
                ps[bi * 64 + lane + 32] = x1 * inv;
            }
            __syncthreads();

            {
                const int row = tid >> 8;
                const int d = (tid & 255) * 4;
                float4 a0 = make_float4(0.f, 0.f, 0.f, 0.f);
                const float* pr = ps + row * 64;
#pragma unroll 4
                for (int t = 0; t < T_CAP; t++) {
                    float p = pr[t];
                    float4 x = *(const float4*)&dh[(long)(t * BATCH + b0 + row) * DEC + d];
                    a0.x += p * x.x; a0.y += p * x.y; a0.z += p * x.z; a0.w += p * x.w;
                }
                __half2 lo = __floats2half2_rn(a0.x, a0.y);
                __half2 hi = __floats2half2_rn(a0.z, a0.w);
                uint2 pk;
                pk.x = *(uint32_t*)&lo;
                pk.y = *(uint32_t*)&hi;
                *(uint2*)&g_ctx_h[(long)(b0 + row) * DEC + d] = pk;
            }
        }
        gsync(&sense);

        // ===== gates: 128m x 64j x 2048k fp16; 4-way k-split, race-free quad loop =====
        {
            const int NS = 32;   // BK=64 stages
            const int NQ = 8;    // quads of 4 stages

            auto load_stage = [&](int ks) {
                int sl = ks & 7;
                int k0 = ks * 64;
                int kb = k0 & 1023;
                const __half* Asrc = ((k0 < 1024) ? g_ctx_h : hprev_h) + a_goff + kb;
                const __half* Bsrc = ((k0 < 1024) ? g_Wih_h : g_Whh_h) + b_goff + kb;
                char* Ab = smem_c + SM_A(sl);
                char* Bb = smem_c + SM_B(sl);
                cp16cg(Ab + SWZ(a_so),      Asrc);
                cp16cg(Ab + SWZ(a_so + 16), Asrc + 8);
                cp16(Bb + SWZ(b_so), Bsrc);
                CP_COMMIT();
            };

            float acc[4][4][4];
#pragma unroll
            for (int i = 0; i < 4; i++)
#pragma unroll
                for (int j = 0; j < 4; j++)
#pragma unroll
                    for (int k = 0; k < 4; k++) acc[i][j][k] = 0.0f;

            // preload quad 0
#pragma unroll
            for (int p = 0; p < 4; p++) load_stage(p);

            for (int t = 0; t < NQ; t++) {
                // barrier 1: all warps done computing quad t-1 -> safe to overwrite its slots
                __syncthreads();
                if (t + 1 < NQ) {
                    int f = 4 * (t + 1);
                    load_stage(f);
                    load_stage(f + 1);
                    load_stage(f + 2);
                    load_stage(f + 3);
                    CP_WAIT(4);      // quad t's loads (issued last iter) complete
                } else {
                    CP_WAIT(0);
                }
                // barrier 2: quad t's data visible to all warps
                __syncthreads();

                const int sl = (4 * t + grp) & 7;
                const uint32_t Ab = smem_base + SM_A(sl);
                const uint32_t Bb = smem_base + SM_B(sl);
#pragma unroll
                for (int kk = 0; kk < 4; kk++) {
                    const uint32_t kofs = (uint32_t)(kk * 32);
                    uint32_t af[4][4], bfa[4], bfb[4];
                    ldsm4(af[0], Ab + (a_swz ^ kofs));
                    ldsm4(af[1], Ab + 2048 + (a_swz ^ kofs));
                    ldsm4(af[2], Ab + 4096 + (a_swz ^ kofs));
                    ldsm4(af[3], Ab + 6144 + (a_swz ^ kofs));
                    ldsm4(bfa, Bb + (b_swz ^ kofs));
                    ldsm4(bfb, Bb + 2048 + (b_swz ^ kofs));
                    uint32_t b0[2] = {bfa[0], bfa[2]};
                    uint32_t b1[2] = {bfa[1], bfa[3]};
                    uint32_t b2[2] = {bfb[0], bfb[2]};
                    uint32_t b3[2] = {bfb[1], bfb[3]};
#pragma unroll
                    for (int fm = 0; fm < 4; fm++) {
                        mma16(acc[fm][0], af[fm], b0);
                        mma16(acc[fm][1], af[fm], b1);
                        mma16(acc[fm][2], af[fm], b2);
                        mma16(acc[fm][3], af[fm], b3);
                    }
                }
            }

            __syncthreads();  // stage smem dead; overlay two gates tiles

            float (*gs0)[68] = (float(*)[68])smem;            // groups 0,2
            float (*gs1)[68] = (float(*)[68])(smem + 8704);   // groups 1,3
            if (grp < 2) {
                float (*gs)[68] = (grp == 0) ? gs0 : gs1;
#pragma unroll
                for (int fm = 0; fm < 4; fm++) {
#pragma unroll
                    for (int fn = 0; fn < 4; fn++) {
                        int m = wm + fm * 16 + lr;
                        int j = wn + fn * 8 + 2 * lc;
                        *(float2*)&gs[m][j]     = make_float2(acc[fm][fn][0], acc[fm][fn][1]);
                        *(float2*)&gs[m + 8][j] = make_float2(acc[fm][fn][2], acc[fm][fn][3]);
                    }
                }
            }
            __syncthreads();
            if (grp >= 2) {
                float (*gs)[68] = (grp == 2) ? gs0 : gs1;
#pragma unroll
                for (int fm = 0; fm < 4; fm++) {
#pragma unroll
                    for (int fn = 0; fn < 4; fn++) {
                        int m = wm + fm * 16 + lr;
                        int j = wn + fn * 8 + 2 * lc;
                        float2 u0 = *(float2*)&gs[m][j];
                        float2 u1 = *(float2*)&gs[m + 8][j];
                        u0.x += acc[fm][fn][0]; u0.y += acc[fm][fn][1];
                        u1.x += acc[fm][fn][2]; u1.y += acc[fm][fn][3];
                        *(float2*)&gs[m][j]     = u0;
                        *(float2*)&gs[m + 8][j] = u1;
                    }
                }
            }
            __syncthreads();

            for (int q = tid; q < 128 * 16; q += NTHR) {
                int ml = q & 127, nl = q >> 7;
                float4 ga = *(float4*)&gs0[ml][nl * 4];
                float4 gb = *(float4*)&gs1[ml][nl * 4];
                float iv = ga.x + gb.x + bias_s[nl * 4 + 0];
                float fv = ga.y + gb.y + bias_s[nl * 4 + 1];
                float gv = ga.z + gb.z + bias_s[nl * 4 + 2];
                float ov = ga.w + gb.w + bias_s[nl * 4 + 3];
                int b = gm0 + ml, n = gn0 + nl;
                int idx = b * HID + n;
                float cold = g_c[idx];
                float cn = sigf(fv) * cold + sigf(iv) * tanhf(gv);
                float hn = sigf(ov) * tanhf(cn);
                g_c[idx] = cn;
                hnext[idx]   = hn;
                hnext_h[idx] = __float2half_rn(hn);
                out[(long)(b * T_feat + s) * HID + n] = hn;
            }
        }
        gsync(&sense);
    }

    gsync(&sense);  // total barriers even -> g_flag restored to 0
}

// ---------------- launcher ----------------
extern "C" void kernel_launch(void* const* d_in, const int* in_sizes, int n_in,
                              void* d_out, int out_size)
{
    int base = 2;
    if (n_in >= 11 && in_sizes[2] == 1) base = 3;

    const float* dh     = (const float*)d_in[0];
    const int*   caps   = (const int*)d_in[1];
    const float* W_attn = (const float*)d_in[base + 0];
    const float* U_attn = (const float*)d_in[base + 1];
    const float* b_attn = (const float*)d_in[base + 2];
    const float* w_attn = (const float*)d_in[base + 3];
    const float* W_ih   = (const float*)d_in[base + 4];
    const float* W_hh   = (const float*)d_in[base + 5];
    const float* b_ih   = (const float*)d_in[base + 6];
    const float* b_hh   = (const float*)d_in[base + 7];
    float* out = (float*)d_out;

    const int T_feat = out_size / (BATCH * HID);  // 28

    static int configured = 0;
    if (!configured) {
        cudaFuncSetAttribute(recon_kernel, cudaFuncAttributeMaxDynamicSharedMemorySize,
                             GK_SMEM_BYTES);
        configured = 1;
    }

    recon_kernel<<<NBLK, NTHR, GK_SMEM_BYTES>>>(
        dh, caps, W_attn, U_attn, b_attn, w_attn,
        W_ih, W_hh, b_ih, b_hh, out, T_feat);
}

// round 11
// speedup vs baseline: 1.1274x; 1.1274x over previous
#include <cuda_runtime.h>
#include <cuda_fp16.h>
#include <cstdint>

#define T_CAP 64
#define BATCH 256
#define DEC   1024
#define HID   1024
#define ATTN  128
#define NBLK  128
#define NTHR  512

// ---------------- persistent scratch ----------------
__device__ float  g_Uv[BATCH * T_CAP * ATTN];   // 8 MB, [b][t][a]
__device__ __half g_h_h[2][BATCH * HID];        // fp16 hidden (gates + attention)
__device__ float  g_c[BATCH * HID];             // cell state (block-private tiles)
__device__ __half g_ctx_h[BATCH * DEC];         // fp16 context
__device__ __half g_Wih_h[4 * HID * DEC];       // fp16 W_ih (8 MB)
__device__ __half g_Whh_h[4 * HID * HID];       // fp16 W_hh (8 MB)
__device__ __half g_Wa_h[ATTN * HID];           // fp16 W_attn (256 KB)
__device__ __half g_dh_h[T_CAP * BATCH * DEC];  // fp16 feats (32 MB)
__device__ int    g_cnt;
__device__ volatile int g_flag;

// ---------------- helpers ----------------
__device__ __forceinline__ uint32_t f2tf(float f) {
    uint32_t u;
    asm("cvt.rna.tf32.f32 %0, %1;" : "=r"(u) : "f"(f));
    return u;
}

__device__ __forceinline__ void mma8(float* c, const uint32_t* a, const uint32_t* b) {
    asm volatile(
        "mma.sync.aligned.m16n8k8.row.col.f32.tf32.tf32.f32 "
        "{%0,%1,%2,%3}, {%4,%5,%6,%7}, {%8,%9}, {%0,%1,%2,%3};\n"
        : "+f"(c[0]), "+f"(c[1]), "+f"(c[2]), "+f"(c[3])
        : "r"(a[0]), "r"(a[1]), "r"(a[2]), "r"(a[3]),
          "r"(b[0]), "r"(b[1]));
}

__device__ __forceinline__ void mma16(float* c, const uint32_t* a, const uint32_t* b) {
    asm volatile(
        "mma.sync.aligned.m16n8k16.row.col.f32.f16.f16.f32 "
        "{%0,%1,%2,%3}, {%4,%5,%6,%7}, {%8,%9}, {%0,%1,%2,%3};\n"
        : "+f"(c[0]), "+f"(c[1]), "+f"(c[2]), "+f"(c[3])
        : "r"(a[0]), "r"(a[1]), "r"(a[2]), "r"(a[3]),
          "r"(b[0]), "r"(b[1]));
}

__device__ __forceinline__ void ldsm4(uint32_t* r, uint32_t addr) {
    asm volatile("ldmatrix.sync.aligned.m8n8.x4.shared.b16 {%0,%1,%2,%3}, [%4];"
                 : "=r"(r[0]), "=r"(r[1]), "=r"(r[2]), "=r"(r[3]) : "r"(addr));
}

__device__ __forceinline__ uint32_t smem_u32(const void* p) {
    return (uint32_t)__cvta_generic_to_shared(p);
}
__device__ __forceinline__ void cp16(void* s, const void* g) {
    asm volatile("cp.async.ca.shared.global [%0], [%1], 16;\n" :: "r"(smem_u32(s)), "l"(g));
}
__device__ __forceinline__ void cp16cg(void* s, const void* g) {
    asm volatile("cp.async.cg.shared.global [%0], [%1], 16;\n" :: "r"(smem_u32(s)), "l"(g));
}
#define CP_COMMIT() asm volatile("cp.async.commit_group;\n" ::)
#define CP_WAIT(n)  asm volatile("cp.async.wait_group " #n ";\n" ::)

__device__ __forceinline__ float sigf(float x) { return 1.0f / (1.0f + __expf(-x)); }
__device__ __forceinline__ float tanh_fast(float x) {
    return __fdividef(2.0f, 1.0f + __expf(-2.0f * x)) - 1.0f;
}

#define SWZ(x) ((x) ^ (((x) >> 3) & 0x70))

// grid barrier (all NBLK blocks co-resident)
__device__ __forceinline__ void gsync(int* sense) {
    __syncthreads();
    int s = *sense ^ 1;
    *sense = s;
    if (threadIdx.x == 0) {
        __threadfence();
        if (atomicAdd(&g_cnt, 1) == NBLK - 1) {
            g_cnt = 0;
            __threadfence();
            g_flag = s;
        } else {
            while (g_flag != s) __nanosleep(32);
        }
        __threadfence();
    }
    __syncthreads();
}

// ---------------- Uv tile: 128(m) x 64(n) x 1024(k), one-time (fp32 inputs) ----------------
__device__ __forceinline__ void uv_tile(
    float* smem, const float* __restrict__ dh, const float* __restrict__ U_attn,
    const float* __restrict__ b_attn, int m0, int n0)
{
    float (*As)[128][20] = (float(*)[128][20])smem;
    float (*Bs)[64][20]  = (float(*)[64][20])(smem + 5120);

    const int tid = threadIdx.x;
    const int warp = tid >> 5, lane = tid & 31;
    const int am = (tid & 255) >> 1, ak = (tid & 1) * 8;
    const int bj = (tid & 255) >> 2, bk = (tid & 3) * 4;
    const int r = m0 + am;
    const long abase = ((long)((r & 63) * 256 + (r >> 6))) * 1024;
    const long bbase = (long)(n0 + bj) * 1024;
    const bool ldr = tid < 256;

    const int wm = (warp >> 2) * 64, wn = (warp & 3) * 16;
    const int lr = lane >> 2, lc = lane & 3;

    float acc[4][2][4];
#pragma unroll
    for (int i = 0; i < 4; i++)
#pragma unroll
        for (int j = 0; j < 2; j++)
#pragma unroll
            for (int k = 0; k < 4; k++) acc[i][j][k] = 0.0f;

    const int NS = 64;
    if (ldr) {
        cp16(&As[0][am][ak],     dh + abase + ak);
        cp16(&As[0][am][ak + 4], dh + abase + ak + 4);
        cp16(&Bs[0][bj][bk],     U_attn + bbase + bk);
    }
    CP_COMMIT();

    for (int s = 0; s < NS; s++) {
        if (s + 1 < NS) {
            int buf = (s + 1) & 1, k0 = (s + 1) * 16;
            if (ldr) {
                cp16(&As[buf][am][ak],     dh + abase + k0 + ak);
                cp16(&As[buf][am][ak + 4], dh + abase + k0 + ak + 4);
                cp16(&Bs[buf][bj][bk],     U_attn + bbase + k0 + bk);
            }
            CP_COMMIT();
            CP_WAIT(1);
        } else {
            CP_WAIT(0);
        }
        __syncthreads();
        if (warp < 8) {
            const int buf = s & 1;
#pragma unroll
            for (int kk = 0; kk < 16; kk += 8) {
                uint32_t af[4][4], bf[2][2];
#pragma unroll
                for (int fm = 0; fm < 4; fm++) {
                    int rr = wm + fm * 16 + lr;
                    af[fm][0] = f2tf(As[buf][rr][kk + lc]);
                    af[fm][1] = f2tf(As[buf][rr + 8][kk + lc]);
                    af[fm][2] = f2tf(As[buf][rr][kk + lc + 4]);
                    af[fm][3] = f2tf(As[buf][rr + 8][kk + lc + 4]);
                }
#pragma unroll
                for (int fn = 0; fn < 2; fn++) {
                    int jc = wn + fn * 8 + lr;
                    bf[fn][0] = f2tf(Bs[buf][jc][kk + lc]);
                    bf[fn][1] = f2tf(Bs[buf][jc][kk + lc + 4]);
                }
#pragma unroll
                for (int fm = 0; fm < 4; fm++)
#pragma unroll
                    for (int fn = 0; fn < 2; fn++) mma8(acc[fm][fn], af[fm], bf[fn]);
            }
        }
        __syncthreads();
    }

    if (warp < 8) {
#pragma unroll
        for (int fm = 0; fm < 4; fm++) {
#pragma unroll
            for (int fn = 0; fn < 2; fn++) {
                int rr = m0 + wm + fm * 16 + lr;
                int a  = n0 + wn + fn * 8 + 2 * lc;
                float ba0 = b_attn[a], ba1 = b_attn[a + 1];
                float2 v0 = make_float2(acc[fm][fn][0] + ba0, acc[fm][fn][1] + ba1);
                float2 v1 = make_float2(acc[fm][fn][2] + ba0, acc[fm][fn][3] + ba1);
                *(float2*)&g_Uv[rr * ATTN + a]       = v0;
                *(float2*)&g_Uv[(rr + 8) * ATTN + a] = v1;
            }
        }
    }
}

// smem (bytes): A stages 8 x 16KB = 128KB ; B stages 8 x 8KB = 64KB
#define SM_A(sl)  ((sl) * 16384)
#define SM_B(sl)  (131072 + (sl) * 8192)
#define GK_SMEM_BYTES 196608

// ---------------- the persistent kernel ----------------
__global__ __launch_bounds__(NTHR, 1) void recon_kernel(
    const float* __restrict__ dh, const int* __restrict__ caps,
    const float* __restrict__ W_attn, const float* __restrict__ U_attn,
    const float* __restrict__ b_attn, const float* __restrict__ w_attn,
    const float* __restrict__ W_ih, const float* __restrict__ W_hh,
    const float* __restrict__ b_ih, const float* __restrict__ b_hh,
    float* __restrict__ out, int T_feat)
{
    extern __shared__ __align__(1024) float smem[];
    __shared__ float bias_s[64];

    const int tid = threadIdx.x, blk = blockIdx.x;
    const int warp = tid >> 5, lane = tid & 31;
    int sense = 0;

    const int gm0 = (blk & 1) * 128;
    const int gn0 = (blk >> 1) * 16;

    char* smem_c = (char*)smem;
    const uint32_t smem_base = smem_u32(smem);

    if (tid < 64) {
        int row = (tid & 3) * 1024 + gn0 + (tid >> 2);
        bias_s[tid] = b_ih[row] + b_hh[row];
    }

    // ---- phase 0: init + fp16 conversions + Uv ----
    for (int i = blk * NTHR + tid; i < BATCH * HID; i += NBLK * NTHR) {
        g_h_h[0][i] = __float2half_rn(0.0f);
        g_c[i]      = 0.0f;
    }
    for (int i = blk * NTHR + tid; i < 4 * HID * DEC; i += NBLK * NTHR)
        g_Wih_h[i] = __float2half_rn(W_ih[i]);
    for (int i = blk * NTHR + tid; i < 4 * HID * HID; i += NBLK * NTHR)
        g_Whh_h[i] = __float2half_rn(W_hh[i]);
    for (int i = blk * NTHR + tid; i < ATTN * HID; i += NBLK * NTHR)
        g_Wa_h[i] = __float2half_rn(W_attn[i]);
    for (int i = blk * NTHR + tid; i < (T_CAP * BATCH * DEC) / 8; i += NBLK * NTHR) {
        float4 x = ((const float4*)dh)[2 * i];
        float4 y = ((const float4*)dh)[2 * i + 1];
        __half2 p0 = __floats2half2_rn(x.x, x.y);
        __half2 p1 = __floats2half2_rn(x.z, x.w);
        __half2 p2 = __floats2half2_rn(y.x, y.y);
        __half2 p3 = __floats2half2_rn(y.z, y.w);
        uint4 pk;
        pk.x = *(uint32_t*)&p0; pk.y = *(uint32_t*)&p1;
        pk.z = *(uint32_t*)&p2; pk.w = *(uint32_t*)&p3;
        ((uint4*)g_dh_h)[i] = pk;
    }
    for (int tix = blk; tix < 256; tix += NBLK)
        uv_tile(smem, dh, U_attn, b_attn, (tix & 127) * 128, (tix >> 7) * 64);
    gsync(&sense);

    // ---- gates loaders: A 128 rows x 64k fp16 (16KB), B 64 j x 64k fp16 (8KB) ----
    const int a_row = tid >> 2;
    const int a_c   = (tid & 3) * 16;
    const long a_goff = (long)(gm0 + a_row) * 1024 + a_c;
    const int a_so  = a_row * 128 + a_c * 2;
    const int b_row = tid >> 3;
    const int b_c   = (tid & 7) * 8;
    const long b_goff = (long)((b_row & 3) * 1024 + gn0 + (b_row >> 2)) * 1024 + b_c;
    const int b_so  = b_row * 128 + b_c * 2;

    // ---- R8 k-split: 2 groups x 8 warps; warp tile 32m x 32j (4m x 2j grid) ----
    const int grp = warp >> 3;          // 0: even stages, 1: odd stages
    const int wg  = warp & 7;
    const int wm  = (wg & 3) * 32;
    const int wn  = (wg >> 2) * 32;
    const int ls_row = ((lane >> 3) & 1) * 8 + (lane & 7);
    const int ls_colb = (lane >> 4) * 16;
    const uint32_t a_swz = SWZ((uint32_t)((wm + ls_row) * 128 + ls_colb));
    const uint32_t b_swz = SWZ((uint32_t)((wn + ls_row) * 128 + ls_colb));
    const int lr = lane >> 2, lc = lane & 3;

    for (int s = 0; s < T_feat; s++) {
        const __half* hprev_h = g_h_h[s & 1];
        __half* hnext_h = g_h_h[(s + 1) & 1];

        // ================= attention: 2 batch rows per block (fp16 inputs) =================
        {
            const int b0 = blk * 2;
            __half* hs_h = (__half*)smem;      // [2][1024] halves = 4 KB
            float* whs = smem + 1024;          // [2][128]
            float* wa  = smem + 1280;          // [128]
            float* es  = smem + 1536;          // [2][64]
            float* ps  = smem + 1664;          // [2][64]

            if (tid < 256)
                cp16cg(hs_h + tid * 8, (const __half*)hprev_h + b0 * HID + tid * 8);
            CP_COMMIT();
            if (tid < ATTN) wa[tid] = w_attn[tid];
            CP_WAIT(0);
            __syncthreads();

            // Wh: warp w owns 8 a-cols; fp16 W and h, fp32 accumulate
            const uint4* hs4 = (const uint4*)hs_h;
#pragma unroll
            for (int rr = 0; rr < 8; rr++) {
                int a = warp * 8 + rr;
                const uint4* wrow = (const uint4*)(g_Wa_h + a * 1024);
                float d0 = 0.f, d1 = 0.f;
#pragma unroll
                for (int j = 0; j < 4; j++) {
                    uint4 w4 = wrow[j * 32 + lane];
                    uint4 x4 = hs4[j * 32 + lane];
                    uint4 y4 = hs4[128 + j * 32 + lane];
                    const __half2* wh2 = (const __half2*)&w4;
                    const __half2* xh2 = (const __half2*)&x4;
                    const __half2* yh2 = (const __half2*)&y4;
#pragma unroll
                    for (int q = 0; q < 4; q++) {
                        float2 wf = __half22float2(wh2[q]);
                        float2 xf = __half22float2(xh2[q]);
                        float2 yf = __half22float2(yh2[q]);
                        d0 += wf.x * xf.x + wf.y * xf.y;
                        d1 += wf.x * yf.x + wf.y * yf.y;
                    }
                }
#pragma unroll
                for (int off = 16; off; off >>= 1) {
                    d0 += __shfl_xor_sync(0xffffffffu, d0, off);
                    d1 += __shfl_xor_sync(0xffffffffu, d1, off);
                }
                if (lane == 0) { whs[a] = d0; whs[128 + a] = d1; }
            }
            __syncthreads();

            for (int t = warp; t < T_CAP; t += 16) {
#pragma unroll
                for (int bi = 0; bi < 2; bi++) {
                    const float* uv = g_Uv + ((long)(b0 + bi) * T_CAP + t) * ATTN;
                    float sE = 0.f;
#pragma unroll
                    for (int q = 0; q < 4; q++) {
                        int a = lane + q * 32;
                        sE += wa[a] * tanh_fast(whs[bi * 128 + a] + uv[a]);
                    }
#pragma unroll
                    for (int off = 16; off; off >>= 1)
                        sE += __shfl_xor_sync(0xffffffffu, sE, off);
                    if (lane == 0) {
                        int cp = caps[t * BATCH + b0 + bi];
                        es[bi * 64 + t] = (cp != 0 && cp != 2) ? sE : -1e30f;
                    }
                }
            }
            __syncthreads();

            if (warp < 2) {
                int bi = warp;
                float e0 = es[bi * 64 + lane], e1 = es[bi * 64 + lane + 32];
                float mx = fmaxf(e0, e1);
#pragma unroll
                for (int off = 16; off; off >>= 1)
                    mx = fmaxf(mx, __shfl_xor_sync(0xffffffffu, mx, off));
                float x0 = __expf(e0 - mx), x1 = __expf(e1 - mx);
                float sm = x0 + x1;
#pragma unroll
                for (int off = 16; off; off >>= 1)
                    sm += __shfl_xor_sync(0xffffffffu, sm, off);
                float inv = 1.0f / sm;
                ps[bi * 64 + lane]      = x0 * inv;
                ps[bi * 64 + lane + 32] = x1 * inv;
            }
            __syncthreads();

            // ctx from fp16 feats, fp32 accumulate
            {
                const int row = tid >> 8;
                const int d4 = (tid & 255) * 4;
                float a0 = 0.f, a1 = 0.f, a2 = 0.f, a3 = 0.f;
                const float* pr = ps + row * 64;
#pragma unroll 4
                for (int t = 0; t < T_CAP; t++) {
                    float p = pr[t];
                    uint2 v = *(const uint2*)&g_dh_h[(long)(t * BATCH + b0 + row) * DEC + d4];
                    float2 f0 = __half22float2(*(__half2*)&v.x);
                    float2 f1 = __half22float2(*(__half2*)&v.y);
                    a0 += p * f0.x; a1 += p * f0.y; a2 += p * f1.x; a3 += p * f1.y;
                }
                __half2 o0 = __floats2half2_rn(a0, a1);
                __half2 o1 = __floats2half2_rn(a2, a3);
                uint2 pk;
                pk.x = *(uint32_t*)&o0;
                pk.y = *(uint32_t*)&o1;
                *(uint2*)&g_ctx_h[(long)(b0 + row) * DEC + d4] = pk;
            }
        }
        gsync(&sense);

        // ===== gates (R8 structure): 128m x 64j x 2048k fp16; pair k-split =====
        {
            const int NS = 32;   // BK=64 stages
            const int NP = 16;   // stage pairs

            auto load_stage = [&](int ks) {
                int sl = ks & 7;
                int k0 = ks * 64;
                int kb = k0 & 1023;
                const __half* Asrc = ((k0 < 1024) ? g_ctx_h : hprev_h) + a_goff + kb;
                const __half* Bsrc = ((k0 < 1024) ? g_Wih_h : g_Whh_h) + b_goff + kb;
                char* Ab = smem_c + SM_A(sl);
                char* Bb = smem_c + SM_B(sl);
                cp16cg(Ab + SWZ(a_so),      Asrc);
                cp16cg(Ab + SWZ(a_so + 16), Asrc + 8);
                cp16(Bb + SWZ(b_so), Bsrc);
                CP_COMMIT();
            };

            float acc[2][4][4];
#pragma unroll
            for (int i = 0; i < 2; i++)
#pragma unroll
                for (int j = 0; j < 4; j++)
#pragma unroll
                    for (int k = 0; k < 4; k++) acc[i][j][k] = 0.0f;

            // preload 4 stages (2 pairs)
#pragma unroll
            for (int p = 0; p < 4; p++) load_stage(p);

            for (int t = 0; t < NP; t++) {
                int f = 2 * t + 4;
                if (f < NS)     load_stage(f);
                if (f + 1 < NS) load_stage(f + 1);
                if (t <= NP - 3)      { CP_WAIT(4); }
                else if (t == NP - 2) { CP_WAIT(2); }
                else                  { CP_WAIT(0); }
                __syncthreads();

                const int sl = (2 * t + grp) & 7;
                const uint32_t Ab = smem_base + SM_A(sl);
                const uint32_t Bb = smem_base + SM_B(sl);
#pragma unroll
                for (int kk = 0; kk < 4; kk++) {
                    const uint32_t kofs = (uint32_t)(kk * 32);
                    uint32_t af0[4], af1[4], bfa[4], bfb[4];
                    ldsm4(af0, Ab + (a_swz ^ kofs));
                    ldsm4(af1, Ab + 2048 + (a_swz ^ kofs));
                    ldsm4(bfa, Bb + (b_swz ^ kofs));
                    ldsm4(bfb, Bb + 2048 + (b_swz ^ kofs));
                    uint32_t b0[2] = {bfa[0], bfa[2]};
                    uint32_t b1[2] = {bfa[1], bfa[3]};
                    uint32_t b2[2] = {bfb[0], bfb[2]};
                    uint32_t b3[2] = {bfb[1], bfb[3]};
                    mma16(acc[0][0], af0, b0);
                    mma16(acc[0][1], af0, b1);
                    mma16(acc[0][2], af0, b2);
                    mma16(acc[0][3], af0, b3);
                    mma16(acc[1][0], af1, b0);
                    mma16(acc[1][1], af1, b1);
                    mma16(acc[1][2], af1, b2);
                    mma16(acc[1][3], af1, b3);
                }
            }

            __syncthreads();  // stage smem dead; overlay gates tile

            float (*gs)[68] = (float(*)[68])smem;
            if (grp == 0) {
#pragma unroll
                for (int fm = 0; fm < 2; fm++) {
#pragma unroll
                    for (int fn = 0; fn < 4; fn++) {
                        int m = wm + fm * 16 + lr;
                        int j = wn + fn * 8 + 2 * lc;
                        *(float2*)&gs[m][j]     = make_float2(acc[fm][fn][0], acc[fm][fn][1]);
                        *(float2*)&gs[m + 8][j] = make_float2(acc[fm][fn][2], acc[fm][fn][3]);
                    }
                }
            }
            __syncthreads();
            if (grp == 1) {
#pragma unroll
                for (int fm = 0; fm < 2; fm++) {
#pragma unroll
                    for (int fn = 0; fn < 4; fn++) {
                        int m = wm + fm * 16 + lr;
                        int j = wn + fn * 8 + 2 * lc;
                        float2 u0 = *(float2*)&gs[m][j];
                        float2 u1 = *(float2*)&gs[m + 8][j];
                        u0.x += acc[fm][fn][0]; u0.y += acc[fm][fn][1];
                        u1.x += acc[fm][fn][2]; u1.y += acc[fm][fn][3];
                        *(float2*)&gs[m][j]     = u0;
                        *(float2*)&gs[m + 8][j] = u1;
                    }
                }
            }
            __syncthreads();

            for (int q = tid; q < 128 * 16; q += NTHR) {
                int ml = q & 127, nl = q >> 7;
                float4 g4 = *(float4*)&gs[ml][nl * 4];
                float iv = g4.x + bias_s[nl * 4 + 0];
                float fv = g4.y + bias_s[nl * 4 + 1];
                float gv = g4.z + bias_s[nl * 4 + 2];
                float ov = g4.w + bias_s[nl * 4 + 3];
                int b = gm0 + ml, n = gn0 + nl;
                int idx = b * HID + n;
                float cold = g_c[idx];
                float cn = sigf(fv) * cold + sigf(iv) * tanhf(gv);
                float hn = sigf(ov) * tanhf(cn);
                g_c[idx] = cn;
                hnext_h[idx] = __float2half_rn(hn);
                out[(long)(b * T_feat + s) * HID + n] = hn;
            }
        }
        gsync(&sense);
    }

    gsync(&sense);  // total barriers even -> g_flag restored to 0
}

// ---------------- launcher ----------------
extern "C" void kernel_launch(void* const* d_in, const int* in_sizes, int n_in,
                              void* d_out, int out_size)
{
    int base = 2;
    if (n_in >= 11 && in_sizes[2] == 1) base = 3;

    const float* dh     = (const float*)d_in[0];
    const int*   caps   = (const int*)d_in[1];
    const float* W_attn = (const float*)d_in[base + 0];
    const float* U_attn = (const float*)d_in[base + 1];
    const float* b_attn = (const float*)d_in[base + 2];
    const float* w_attn = (const float*)d_in[base + 3];
    const float* W_ih   = (const float*)d_in[base + 4];
    const float* W_hh   = (const float*)d_in[base + 5];
    const float* b_ih   = (const float*)d_in[base + 6];
    const float* b_hh   = (const float*)d_in[base + 7];
    float* out = (float*)d_out;

    const int T_feat = out_size / (BATCH * HID);  // 28

    static int configured = 0;
    if (!configured) {
        cudaFuncSetAttribute(recon_kernel, cudaFuncAttributeMaxDynamicSharedMemorySize,
                             GK_SMEM_BYTES);
        configured = 1;
    }

    recon_kernel<<<NBLK, NTHR, GK_SMEM_BYTES>>>(
        dh, caps, W_attn, U_attn, b_attn, w_attn,
        W_ih, W_hh, b_ih, b_hh, out, T_feat);
}

// round 12
// speedup vs baseline: 1.1319x; 1.0040x over previous
#include <cuda_runtime.h>
#include <cuda_fp16.h>
#include <cstdint>

#define T_CAP 64
#define BATCH 256
#define DEC   1024
#define HID   1024
#define ATTN  128
#define NBLK  128
#define NTHR  512

// ---------------- persistent scratch ----------------
__device__ float  g_Uv[BATCH * T_CAP * ATTN];   // 8 MB, [b][t][a]
__device__ __half g_h_h[2][BATCH * HID];        // fp16 hidden (gates + attention)
__device__ float  g_c[BATCH * HID];             // cell state (block-private tiles)
__device__ __half g_ctx_h[BATCH * DEC];         // fp16 context
__device__ __half g_Wih_h[4 * HID * DEC];       // fp16 W_ih (8 MB)
__device__ __half g_Whh_h[4 * HID * HID];       // fp16 W_hh (8 MB)
__device__ __half g_Wa_h[ATTN * HID];           // fp16 W_attn (256 KB)
__device__ __half g_dh_h[T_CAP * BATCH * DEC];  // fp16 feats (32 MB)
__device__ int    g_cnt;
__device__ volatile int g_flag;

// ---------------- helpers ----------------
__device__ __forceinline__ uint32_t f2tf(float f) {
    uint32_t u;
    asm("cvt.rna.tf32.f32 %0, %1;" : "=r"(u) : "f"(f));
    return u;
}

__device__ __forceinline__ void mma8(float* c, const uint32_t* a, const uint32_t* b) {
    asm volatile(
        "mma.sync.aligned.m16n8k8.row.col.f32.tf32.tf32.f32 "
        "{%0,%1,%2,%3}, {%4,%5,%6,%7}, {%8,%9}, {%0,%1,%2,%3};\n"
        : "+f"(c[0]), "+f"(c[1]), "+f"(c[2]), "+f"(c[3])
        : "r"(a[0]), "r"(a[1]), "r"(a[2]), "r"(a[3]),
          "r"(b[0]), "r"(b[1]));
}

__device__ __forceinline__ void mma16(float* c, const uint32_t* a, const uint32_t* b) {
    asm volatile(
        "mma.sync.aligned.m16n8k16.row.col.f32.f16.f16.f32 "
        "{%0,%1,%2,%3}, {%4,%5,%6,%7}, {%8,%9}, {%0,%1,%2,%3};\n"
        : "+f"(c[0]), "+f"(c[1]), "+f"(c[2]), "+f"(c[3])
        : "r"(a[0]), "r"(a[1]), "r"(a[2]), "r"(a[3]),
          "r"(b[0]), "r"(b[1]));
}

__device__ __forceinline__ void ldsm4(uint32_t* r, uint32_t addr) {
    asm volatile("ldmatrix.sync.aligned.m8n8.x4.shared.b16 {%0,%1,%2,%3}, [%4];"
                 : "=r"(r[0]), "=r"(r[1]), "=r"(r[2]), "=r"(r[3]) : "r"(addr));
}

__device__ __forceinline__ uint32_t smem_u32(const void* p) {
    return (uint32_t)__cvta_generic_to_shared(p);
}
__device__ __forceinline__ void cp16(void* s, const void* g) {
    asm volatile("cp.async.ca.shared.global [%0], [%1], 16;\n" :: "r"(smem_u32(s)), "l"(g));
}
__device__ __forceinline__ void cp16cg(void* s, const void* g) {
    asm volatile("cp.async.cg.shared.global [%0], [%1], 16;\n" :: "r"(smem_u32(s)), "l"(g));
}
#define CP_COMMIT() asm volatile("cp.async.commit_group;\n" ::)
#define CP_WAIT(n)  asm volatile("cp.async.wait_group " #n ";\n" ::)

__device__ __forceinline__ float sigf(float x) { return 1.0f / (1.0f + __expf(-x)); }
__device__ __forceinline__ float tanh_fast(float x) {
    return __fdividef(2.0f, 1.0f + __expf(-2.0f * x)) - 1.0f;
}

#define SWZ(x) ((x) ^ (((x) >> 3) & 0x70))

// grid barrier (all NBLK blocks co-resident)
__device__ __forceinline__ void gsync(int* sense) {
    __syncthreads();
    int s = *sense ^ 1;
    *sense = s;
    if (threadIdx.x == 0) {
        __threadfence();
        if (atomicAdd(&g_cnt, 1) == NBLK - 1) {
            g_cnt = 0;
            __threadfence();
            g_flag = s;
        } else {
            while (g_flag != s) __nanosleep(32);
        }
        __threadfence();
    }
    __syncthreads();
}

// ---------------- Uv tile: 128(m) x 64(n) x 1024(k), one-time (fp32 inputs) ----------------
__device__ __forceinline__ void uv_tile(
    float* smem, const float* __restrict__ dh, const float* __restrict__ U_attn,
    const float* __restrict__ b_attn, int m0, int n0)
{
    float (*As)[128][20] = (float(*)[128][20])smem;
    float (*Bs)[64][20]  = (float(*)[64][20])(smem + 5120);

    const int tid = threadIdx.x;
    const int warp = tid >> 5, lane = tid & 31;
    const int am = (tid & 255) >> 1, ak = (tid & 1) * 8;
    const int bj = (tid & 255) >> 2, bk = (tid & 3) * 4;
    const int r = m0 + am;
    const long abase = ((long)((r & 63) * 256 + (r >> 6))) * 1024;
    const long bbase = (long)(n0 + bj) * 1024;
    const bool ldr = tid < 256;

    const int wm = (warp >> 2) * 64, wn = (warp & 3) * 16;
    const int lr = lane >> 2, lc = lane & 3;

    float acc[4][2][4];
#pragma unroll
    for (int i = 0; i < 4; i++)
#pragma unroll
        for (int j = 0; j < 2; j++)
#pragma unroll
            for (int k = 0; k < 4; k++) acc[i][j][k] = 0.0f;

    const int NS = 64;
    if (ldr) {
        cp16(&As[0][am][ak],     dh + abase + ak);
        cp16(&As[0][am][ak + 4], dh + abase + ak + 4);
        cp16(&Bs[0][bj][bk],     U_attn + bbase + bk);
    }
    CP_COMMIT();

    for (int s = 0; s < NS; s++) {
        if (s + 1 < NS) {
            int buf = (s + 1) & 1, k0 = (s + 1) * 16;
            if (ldr) {
                cp16(&As[buf][am][ak],     dh + abase + k0 + ak);
                cp16(&As[buf][am][ak + 4], dh + abase + k0 + ak + 4);
                cp16(&Bs[buf][bj][bk],     U_attn + bbase + k0 + bk);
            }
            CP_COMMIT();
            CP_WAIT(1);
        } else {
            CP_WAIT(0);
        }
        __syncthreads();
        if (warp < 8) {
            const int buf = s & 1;
#pragma unroll
            for (int kk = 0; kk < 16; kk += 8) {
                uint32_t af[4][4], bf[2][2];
#pragma unroll
                for (int fm = 0; fm < 4; fm++) {
                    int rr = wm + fm * 16 + lr;
                    af[fm][0] = f2tf(As[buf][rr][kk + lc]);
                    af[fm][1] = f2tf(As[buf][rr + 8][kk + lc]);
                    af[fm][2] = f2tf(As[buf][rr][kk + lc + 4]);
                    af[fm][3] = f2tf(As[buf][rr + 8][kk + lc + 4]);
                }
#pragma unroll
                for (int fn = 0; fn < 2; fn++) {
                    int jc = wn + fn * 8 + lr;
                    bf[fn][0] = f2tf(Bs[buf][jc][kk + lc]);
                    bf[fn][1] = f2tf(Bs[buf][jc][kk + lc + 4]);
                }
#pragma unroll
                for (int fm = 0; fm < 4; fm++)
#pragma unroll
                    for (int fn = 0; fn < 2; fn++) mma8(acc[fm][fn], af[fm], bf[fn]);
            }
        }
        __syncthreads();
    }

    if (warp < 8) {
#pragma unroll
        for (int fm = 0; fm < 4; fm++) {
#pragma unroll
            for (int fn = 0; fn < 2; fn++) {
                int rr = m0 + wm + fm * 16 + lr;
                int a  = n0 + wn + fn * 8 + 2 * lc;
                float ba0 = b_attn[a], ba1 = b_attn[a + 1];
                float2 v0 = make_float2(acc[fm][fn][0] + ba0, acc[fm][fn][1] + ba1);
                float2 v1 = make_float2(acc[fm][fn][2] + ba0, acc[fm][fn][3] + ba1);
                *(float2*)&g_Uv[rr * ATTN + a]       = v0;
                *(float2*)&g_Uv[(rr + 8) * ATTN + a] = v1;
            }
        }
    }
}

// smem (bytes): A stages 8 x 16KB = 128KB ; B stages 8 x 8KB = 64KB
#define SM_A(sl)  ((sl) * 16384)
#define SM_B(sl)  (131072 + (sl) * 8192)
#define GK_SMEM_BYTES 196608

// ---------------- the persistent kernel ----------------
__global__ __launch_bounds__(NTHR, 1) void recon_kernel(
    const float* __restrict__ dh, const int* __restrict__ caps,
    const float* __restrict__ W_attn, const float* __restrict__ U_attn,
    const float* __restrict__ b_attn, const float* __restrict__ w_attn,
    const float* __restrict__ W_ih, const float* __restrict__ W_hh,
    const float* __restrict__ b_ih, const float* __restrict__ b_hh,
    float* __restrict__ out, int T_feat)
{
    extern __shared__ __align__(1024) float smem[];
    __shared__ float bias_s[64];

    const int tid = threadIdx.x, blk = blockIdx.x;
    const int warp = tid >> 5, lane = tid & 31;
    int sense = 0;

    const int gm0 = (blk & 1) * 128;
    const int gn0 = (blk >> 1) * 16;

    char* smem_c = (char*)smem;
    const uint32_t smem_base = smem_u32(smem);

    if (tid < 64) {
        int row = (tid & 3) * 1024 + gn0 + (tid >> 2);
        bias_s[tid] = b_ih[row] + b_hh[row];
    }

    // ---- phase 0: init + fp16 conversions + Uv ----
    for (int i = blk * NTHR + tid; i < BATCH * HID; i += NBLK * NTHR) {
        g_h_h[0][i] = __float2half_rn(0.0f);
        g_c[i]      = 0.0f;
    }
    for (int i = blk * NTHR + tid; i < 4 * HID * DEC; i += NBLK * NTHR)
        g_Wih_h[i] = __float2half_rn(W_ih[i]);
    for (int i = blk * NTHR + tid; i < 4 * HID * HID; i += NBLK * NTHR)
        g_Whh_h[i] = __float2half_rn(W_hh[i]);
    for (int i = blk * NTHR + tid; i < ATTN * HID; i += NBLK * NTHR)
        g_Wa_h[i] = __float2half_rn(W_attn[i]);
    for (int i = blk * NTHR + tid; i < (T_CAP * BATCH * DEC) / 8; i += NBLK * NTHR) {
        float4 x = ((const float4*)dh)[2 * i];
        float4 y = ((const float4*)dh)[2 * i + 1];
        __half2 p0 = __floats2half2_rn(x.x, x.y);
        __half2 p1 = __floats2half2_rn(x.z, x.w);
        __half2 p2 = __floats2half2_rn(y.x, y.y);
        __half2 p3 = __floats2half2_rn(y.z, y.w);
        uint4 pk;
        pk.x = *(uint32_t*)&p0; pk.y = *(uint32_t*)&p1;
        pk.z = *(uint32_t*)&p2; pk.w = *(uint32_t*)&p3;
        ((uint4*)g_dh_h)[i] = pk;
    }
    for (int tix = blk; tix < 256; tix += NBLK)
        uv_tile(smem, dh, U_attn, b_attn, (tix & 127) * 128, (tix >> 7) * 64);
    gsync(&sense);

    // ---- gates loaders: A 128 rows x 64k fp16 (16KB), B 64 j x 64k fp16 (8KB) ----
    const int a_row = tid >> 2;
    const int a_c   = (tid & 3) * 16;
    const long a_goff = (long)(gm0 + a_row) * 1024 + a_c;
    const int a_so  = a_row * 128 + a_c * 2;
    const int b_row = tid >> 3;
    const int b_c   = (tid & 7) * 8;
    const long b_goff = (long)((b_row & 3) * 1024 + gn0 + (b_row >> 2)) * 1024 + b_c;
    const int b_so  = b_row * 128 + b_c * 2;

    // ---- k-split: 2 groups x 8 warps; warp tile 32m x 32j (4m x 2j grid) ----
    const int grp = warp >> 3;
    const int wg  = warp & 7;
    const int wm  = (wg & 3) * 32;
    const int wn  = (wg >> 2) * 32;
    const int ls_row = ((lane >> 3) & 1) * 8 + (lane & 7);
    const int ls_colb = (lane >> 4) * 16;
    const uint32_t a_swz = SWZ((uint32_t)((wm + ls_row) * 128 + ls_colb));
    const uint32_t b_swz = SWZ((uint32_t)((wn + ls_row) * 128 + ls_colb));
    const int lr = lane >> 2, lc = lane & 3;

    for (int s = 0; s < T_feat; s++) {
        const __half* hprev_h = g_h_h[s & 1];
        __half* hnext_h = g_h_h[(s + 1) & 1];

        // gates stage loader: processing order p=0..31 -> stage (p+16)&31 (h-half first),
        // slot (p+4)&7 (preload slots 4-7 avoid attention smem at 0-16KB).
        auto load_stage = [&](int p) {
            int st = (p + 16) & 31;
            int sl = (p + 4) & 7;
            int k0 = st * 64;
            int kb = k0 & 1023;
            const __half* Asrc = ((k0 < 1024) ? g_ctx_h : hprev_h) + a_goff + kb;
            const __half* Bsrc = ((k0 < 1024) ? g_Wih_h : g_Whh_h) + b_goff + kb;
            char* Ab = smem_c + SM_A(sl);
            char* Bb = smem_c + SM_B(sl);
            cp16cg(Ab + SWZ(a_so),      Asrc);
            cp16cg(Ab + SWZ(a_so + 16), Asrc + 8);
            cp16(Bb + SWZ(b_so), Bsrc);
            CP_COMMIT();
        };

        // ================= attention: 2 batch rows per block (fp16 inputs) =================
        {
            const int b0 = blk * 2;
            __half* hs_h = (__half*)smem;      // [2][1024] halves = 4 KB
            float* whs = smem + 1024;          // [2][128]
            float* wa  = smem + 1280;          // [128]
            float* es  = smem + 1536;          // [2][64]
            float* ps  = smem + 1664;          // [2][64]

            if (tid < 256)
                cp16cg(hs_h + tid * 8, (const __half*)hprev_h + b0 * HID + tid * 8);
            CP_COMMIT();
            if (tid < ATTN) wa[tid] = w_attn[tid];
            CP_WAIT(0);
            __syncthreads();

            // Wh: warp w owns 8 a-cols; fp16 W and h, fp32 accumulate
            const uint4* hs4 = (const uint4*)hs_h;
#pragma unroll
            for (int rr = 0; rr < 8; rr++) {
                int a = warp * 8 + rr;
                const uint4* wrow = (const uint4*)(g_Wa_h + a * 1024);
                float d0 = 0.f, d1 = 0.f;
#pragma unroll
                for (int j = 0; j < 4; j++) {
                    uint4 w4 = wrow[j * 32 + lane];
                    uint4 x4 = hs4[j * 32 + lane];
                    uint4 y4 = hs4[128 + j * 32 + lane];
                    const __half2* wh2 = (const __half2*)&w4;
                    const __half2* xh2 = (const __half2*)&x4;
                    const __half2* yh2 = (const __half2*)&y4;
#pragma unroll
                    for (int q = 0; q < 4; q++) {
                        float2 wf = __half22float2(wh2[q]);
                        float2 xf = __half22float2(xh2[q]);
                        float2 yf = __half22float2(yh2[q]);
                        d0 += wf.x * xf.x + wf.y * xf.y;
                        d1 += wf.x * yf.x + wf.y * yf.y;
                    }
                }
#pragma unroll
                for (int off = 16; off; off >>= 1) {
                    d0 += __shfl_xor_sync(0xffffffffu, d0, off);
                    d1 += __shfl_xor_sync(0xffffffffu, d1, off);
                }
                if (lane == 0) { whs[a] = d0; whs[128 + a] = d1; }
            }
            __syncthreads();

            for (int t = warp; t < T_CAP; t += 16) {
#pragma unroll
                for (int bi = 0; bi < 2; bi++) {
                    const float* uv = g_Uv + ((long)(b0 + bi) * T_CAP + t) * ATTN;
                    float sE = 0.f;
#pragma unroll
                    for (int q = 0; q < 4; q++) {
                        int a = lane + q * 32;
                        sE += wa[a] * tanh_fast(whs[bi * 128 + a] + uv[a]);
                    }
#pragma unroll
                    for (int off = 16; off; off >>= 1)
                        sE += __shfl_xor_sync(0xffffffffu, sE, off);
                    if (lane == 0) {
                        int cp = caps[t * BATCH + b0 + bi];
                        es[bi * 64 + t] = (cp != 0 && cp != 2) ? sE : -1e30f;
                    }
                }
            }
            __syncthreads();

            if (warp < 2) {
                int bi = warp;
                float e0 = es[bi * 64 + lane], e1 = es[bi * 64 + lane + 32];
                float mx = fmaxf(e0, e1);
#pragma unroll
                for (int off = 16; off; off >>= 1)
                    mx = fmaxf(mx, __shfl_xor_sync(0xffffffffu, mx, off));
                float x0 = __expf(e0 - mx), x1 = __expf(e1 - mx);
                float sm = x0 + x1;
#pragma unroll
                for (int off = 16; off; off >>= 1)
                    sm += __shfl_xor_sync(0xffffffffu, sm, off);
                float inv = 1.0f / sm;
                ps[bi * 64 + lane]      = x0 * inv;
                ps[bi * 64 + lane + 32] = x1 * inv;
            }
            __syncthreads();

            // ctx from fp16 feats, fp32 accumulate
            {
                const int row = tid >> 8;
                const int d4 = (tid & 255) * 4;
                float a0 = 0.f, a1 = 0.f, a2 = 0.f, a3 = 0.f;
                const float* pr = ps + row * 64;
#pragma unroll 4
                for (int t = 0; t < T_CAP; t++) {
                    float p = pr[t];
                    uint2 v = *(const uint2*)&g_dh_h[(long)(t * BATCH + b0 + row) * DEC + d4];
                    float2 f0 = __half22float2(*(__half2*)&v.x);
                    float2 f1 = __half22float2(*(__half2*)&v.y);
                    a0 += p * f0.x; a1 += p * f0.y; a2 += p * f1.x; a3 += p * f1.y;
                }
                __half2 o0 = __floats2half2_rn(a0, a1);
                __half2 o1 = __floats2half2_rn(a2, a3);
                uint2 pk;
                pk.x = *(uint32_t*)&o0;
                pk.y = *(uint32_t*)&o1;
                *(uint2*)&g_ctx_h[(long)(b0 + row) * DEC + d4] = pk;
            }
        }

        // preload first 4 gates stages (h-half: depends only on hprev + W_hh) — these
        // cp.asyncs fly during the grid barrier; slots 4-7 don't touch attention smem.
        load_stage(0);
        load_stage(1);
        load_stage(2);
        load_stage(3);

        gsync(&sense);

        // ===== gates: 128m x 64j x 2048k fp16; pair k-split, h-half first =====
        {
            const int NP = 16;   // stage pairs

            float acc[2][4][4];
#pragma unroll
            for (int i = 0; i < 2; i++)
#pragma unroll
                for (int j = 0; j < 4; j++)
#pragma unroll
                    for (int k = 0; k < 4; k++) acc[i][j][k] = 0.0f;

            for (int t = 0; t < NP; t++) {
                int f = 2 * t + 4;
                if (f < 32)     load_stage(f);
                if (f + 1 < 32) load_stage(f + 1);
                if (t <= NP - 3)      { CP_WAIT(4); }
                else if (t == NP - 2) { CP_WAIT(2); }
                else                  { CP_WAIT(0); }
                __syncthreads();

                const int sl = (2 * t + grp + 4) & 7;
                const uint32_t Ab = smem_base + SM_A(sl);
                const uint32_t Bb = smem_base + SM_B(sl);
#pragma unroll
                for (int kk = 0; kk < 4; kk++) {
                    const uint32_t kofs = (uint32_t)(kk * 32);
                    uint32_t af0[4], af1[4], bfa[4], bfb[4];
                    ldsm4(af0, Ab + (a_swz ^ kofs));
                    ldsm4(af1, Ab + 2048 + (a_swz ^ kofs));
                    ldsm4(bfa, Bb + (b_swz ^ kofs));
                    ldsm4(bfb, Bb + 2048 + (b_swz ^ kofs));
                    uint32_t b0[2] = {bfa[0], bfa[2]};
                    uint32_t b1[2] = {bfa[1], bfa[3]};
                    uint32_t b2[2] = {bfb[0], bfb[2]};
                    uint32_t b3[2] = {bfb[1], bfb[3]};
                    mma16(acc[0][0], af0, b0);
                    mma16(acc[0][1], af0, b1);
                    mma16(acc[0][2], af0, b2);
                    mma16(acc[0][3], af0, b3);
                    mma16(acc[1][0], af1, b0);
                    mma16(acc[1][1], af1, b1);
                    mma16(acc[1][2], af1, b2);
                    mma16(acc[1][3], af1, b3);
                }
            }

            __syncthreads();  // stage smem dead; overlay two gates tiles

            float (*gs0)[68] = (float(*)[68])smem;            // grp 0
            float (*gs1)[68] = (float(*)[68])(smem + 8704);   // grp 1
            {
                float (*gs)[68] = (grp == 0) ? gs0 : gs1;
#pragma unroll
                for (int fm = 0; fm < 2; fm++) {
#pragma unroll
                    for (int fn = 0; fn < 4; fn++) {
                        int m = wm + fm * 16 + lr;
                        int j = wn + fn * 8 + 2 * lc;
                        *(float2*)&gs[m][j]     = make_float2(acc[fm][fn][0], acc[fm][fn][1]);
                        *(float2*)&gs[m + 8][j] = make_float2(acc[fm][fn][2], acc[fm][fn][3]);
                    }
                }
            }
            __syncthreads();

            for (int q = tid; q < 128 * 16; q += NTHR) {
                int ml = q & 127, nl = q >> 7;
                float4 ga = *(float4*)&gs0[ml][nl * 4];
                float4 gb = *(float4*)&gs1[ml][nl * 4];
                float iv = ga.x + gb.x + bias_s[nl * 4 + 0];
                float fv = ga.y + gb.y + bias_s[nl * 4 + 1];
                float gv = ga.z + gb.z + bias_s[nl * 4 + 2];
                float ov = ga.w + gb.w + bias_s[nl * 4 + 3];
                int b = gm0 + ml, n = gn0 + nl;
                int idx = b * HID + n;
                float cold = g_c[idx];
                float cn = sigf(fv) * cold + sigf(iv) * tanhf(gv);
                float hn = sigf(ov) * tanhf(cn);
                g_c[idx] = cn;
                hnext_h[idx] = __float2half_rn(hn);
                out[(long)(b * T_feat + s) * HID + n] = hn;
            }
        }
        gsync(&sense);
    }

    gsync(&sense);  // total barriers even -> g_flag restored to 0
}

// ---------------- launcher ----------------
extern "C" void kernel_launch(void* const* d_in, const int* in_sizes, int n_in,
                              void* d_out, int out_size)
{
    int base = 2;
    if (n_in >= 11 && in_sizes[2] == 1) base = 3;

    const float* dh     = (const float*)d_in[0];
    const int*   caps   = (const int*)d_in[1];
    const float* W_attn = (const float*)d_in[base + 0];
    const float* U_attn = (const float*)d_in[base + 1];
    const float* b_attn = (const float*)d_in[base + 2];
    const float* w_attn = (const float*)d_in[base + 3];
    const float* W_ih   = (const float*)d_in[base + 4];
    const float* W_hh   = (const float*)d_in[base + 5];
    const float* b_ih   = (const float*)d_in[base + 6];
    const float* b_hh   = (const float*)d_in[base + 7];
    float* out = (float*)d_out;

    const int T_feat = out_size / (BATCH * HID);  // 28

    static int configured = 0;
    if (!configured) {
        cudaFuncSetAttribute(recon_kernel, cudaFuncAttributeMaxDynamicSharedMemorySize,
                             GK_SMEM_BYTES);
        configured = 1;
    }

    recon_kernel<<<NBLK, NTHR, GK_SMEM_BYTES>>>(
        dh, caps, W_attn, U_attn, b_attn, w_attn,
        W_ih, W_hh, b_ih, b_hh, out, T_feat);
}